// round 4
// baseline (speedup 1.0000x reference)
#include <cuda_runtime.h>
#include <math.h>

// Problem constants (fixed by the dataset)
#define N_NODES   170000
#define N_EDGES   1200000
#define D_FEAT    128
#define N_CLASSES 40
#define D4        (D_FEAT / 4)   // 32 float4 per row

#define SCAN_B  1024
#define SCAN_NB ((N_NODES + SCAN_B - 1) / SCAN_B)   // 167

// ---- scratch (device globals; no allocations allowed) ----
__device__ float4 g_h1[(size_t)N_NODES * D4];   // 87 MB
__device__ float4 g_h2[(size_t)N_NODES * D4];   // 87 MB
__device__ int    g_deg[N_NODES];
__device__ int    g_pos[N_NODES];
__device__ int    g_off[N_NODES + 1];
__device__ int    g_bsum[SCAN_NB];
__device__ int    g_srcs[N_EDGES];
__device__ float  g_dinv[N_NODES];
__device__ int    g_is64;   // 1 if edge_index is int64, 0 if int32

// ---- edge accessor: dtype decided at runtime by probe ----
__device__ __forceinline__ int edge_at(const void* ei, int is64, int idx) {
    if (is64) return (int)((const long long*)ei)[idx];
    return ((const int*)ei)[idx];
}
__device__ __forceinline__ int clampN(int v) {
    return ((unsigned)v < (unsigned)N_NODES) ? v : 0;
}

// ---- 0. probe edge dtype: int64 data has all-zero high (odd int32) words ----
__global__ void k_probe(const int* __restrict__ ei32) {
    // lanes inspect odd words 1,3,...,127 of the buffer start
    int lane = threadIdx.x;           // 32 threads
    int w0 = ei32[2 * lane + 1];
    int w1 = ei32[2 * (lane + 32) + 1];
    unsigned nz = __ballot_sync(0xffffffffu, (w0 | w1) != 0);
    if (lane == 0) g_is64 = (nz == 0u) ? 1 : 0;
}

// ---- 1. zero counters ----
__global__ void k_zero() {
    int i = blockIdx.x * blockDim.x + threadIdx.x;
    if (i < N_NODES) { g_deg[i] = 0; g_pos[i] = 0; }
}

// ---- 2. in-degree histogram over dst ----
__global__ void k_count(const void* __restrict__ ei) {
    int e = blockIdx.x * blockDim.x + threadIdx.x;
    int is64 = g_is64;
    if (e < N_EDGES) {
        int d = clampN(edge_at(ei, is64, N_EDGES + e));
        atomicAdd(&g_deg[d], 1);
    }
}

// ---- 3. dinv = rsqrt(indeg + 1)  (self-loop included) ----
__global__ void k_dinv() {
    int i = blockIdx.x * blockDim.x + threadIdx.x;
    if (i < N_NODES) g_dinv[i] = rsqrtf((float)(g_deg[i] + 1));
}

// ---- 4-6. exclusive scan of g_deg -> g_off (3-phase) ----
__global__ void k_scan1() {
    __shared__ int sh[SCAN_B];
    int i = blockIdx.x * SCAN_B + threadIdx.x;
    int v = (i < N_NODES) ? g_deg[i] : 0;
    sh[threadIdx.x] = v;
    __syncthreads();
    for (int d = 1; d < SCAN_B; d <<= 1) {
        int t = (threadIdx.x >= d) ? sh[threadIdx.x - d] : 0;
        __syncthreads();
        sh[threadIdx.x] += t;
        __syncthreads();
    }
    if (i < N_NODES) g_off[i] = sh[threadIdx.x] - v;   // exclusive
    if (threadIdx.x == SCAN_B - 1) g_bsum[blockIdx.x] = sh[SCAN_B - 1];
}

__global__ void k_scan2() {
    __shared__ int sh[256];
    int tid = threadIdx.x;
    int v = (tid < SCAN_NB) ? g_bsum[tid] : 0;
    sh[tid] = v;
    __syncthreads();
    for (int d = 1; d < 256; d <<= 1) {
        int t = (tid >= d) ? sh[tid - d] : 0;
        __syncthreads();
        sh[tid] += t;
        __syncthreads();
    }
    if (tid < SCAN_NB) g_bsum[tid] = sh[tid] - v;      // exclusive block offsets
}

__global__ void k_scan3() {
    int i = blockIdx.x * SCAN_B + threadIdx.x;
    if (i < N_NODES) g_off[i] += g_bsum[blockIdx.x];
    if (i == 0) g_off[N_NODES] = N_EDGES;
}

// ---- 7. scatter edges into CSR-by-dst ----
__global__ void k_scatter(const void* __restrict__ ei) {
    int e = blockIdx.x * blockDim.x + threadIdx.x;
    int is64 = g_is64;
    if (e < N_EDGES) {
        int s = clampN(edge_at(ei, is64, e));
        int d = clampN(edge_at(ei, is64, N_EDGES + e));
        int p = g_off[d] + atomicAdd(&g_pos[d], 1);
        g_srcs[p] = s;
    }
}

// ---- 8. one propagation hop: warp per node ----
// out[i] = dinv[i] * ( sum_{j->i} dinv[j]*h[j] + dinv[i]*h[i] )
__global__ void k_prop(const float4* __restrict__ x4, int pass) {
    const float4* hin  = (pass == 0) ? x4 : g_h1;
    float4*       hout = (pass == 0) ? g_h1 : g_h2;

    int gw = (blockIdx.x * blockDim.x + threadIdx.x) >> 5;
    if (gw >= N_NODES) return;
    int lane = threadIdx.x & 31;

    int beg = g_off[gw];
    int end = g_off[gw + 1];
    float di = g_dinv[gw];

    // self-loop term
    float4 v = hin[(size_t)gw * D4 + lane];
    float ax = di * v.x, ay = di * v.y, az = di * v.z, aw = di * v.w;

    for (int p = beg; p < end; p++) {
        int   s  = g_srcs[p];
        float ds = g_dinv[s];
        float4 u = hin[(size_t)s * D4 + lane];
        ax = fmaf(ds, u.x, ax);
        ay = fmaf(ds, u.y, ay);
        az = fmaf(ds, u.z, az);
        aw = fmaf(ds, u.w, aw);
    }

    float4 o;
    o.x = di * ax; o.y = di * ay; o.z = di * az; o.w = di * aw;
    hout[(size_t)gw * D4 + lane] = o;
}

// ---- 9. logits + fused log_softmax: THREAD per node, W broadcast from smem ----
__global__ void k_classify(const float4* __restrict__ W4,
                           const float*  __restrict__ b,
                           float* __restrict__ out) {
    __shared__ float4 sW[N_CLASSES][D4];   // 20 KB
    __shared__ float  sb[N_CLASSES];
    for (int i = threadIdx.x; i < N_CLASSES * D4; i += blockDim.x)
        (&sW[0][0])[i] = W4[i];
    if (threadIdx.x < N_CLASSES) sb[threadIdx.x] = b[threadIdx.x];
    __syncthreads();

    int node = blockIdx.x * blockDim.x + threadIdx.x;
    if (node >= N_NODES) return;

    float acc[N_CLASSES];
    #pragma unroll
    for (int c = 0; c < N_CLASSES; c++) acc[c] = sb[c];

    const float4* h = g_h2 + (size_t)node * D4;
    #pragma unroll 4
    for (int k = 0; k < D4; k++) {
        float4 hv = h[k];
        #pragma unroll
        for (int c = 0; c < N_CLASSES; c++) {
            float4 w = sW[c][k];           // broadcast: all lanes same address
            acc[c] = fmaf(hv.x, w.x, acc[c]);
            acc[c] = fmaf(hv.y, w.y, acc[c]);
            acc[c] = fmaf(hv.z, w.z, acc[c]);
            acc[c] = fmaf(hv.w, w.w, acc[c]);
        }
    }

    float m = acc[0];
    #pragma unroll
    for (int c = 1; c < N_CLASSES; c++) m = fmaxf(m, acc[c]);
    float s = 0.f;
    #pragma unroll
    for (int c = 0; c < N_CLASSES; c++) s += __expf(acc[c] - m);
    float lse = m + logf(s);

    float* o = out + (size_t)node * N_CLASSES;
    #pragma unroll
    for (int c = 0; c < N_CLASSES; c++) o[c] = acc[c] - lse;
}

extern "C" void kernel_launch(void* const* d_in, const int* in_sizes, int n_in,
                              void* d_out, int out_size) {
    const float4* x4  = (const float4*)d_in[0];
    const void*   ei  = d_in[1];
    const float4* W4  = (const float4*)d_in[2];
    const float*  b   = (const float*)d_in[3];
    float*        out = (float*)d_out;
    (void)in_sizes; (void)n_in; (void)out_size;

    const int TB = 256;
    int nblk_nodes = (N_NODES + TB - 1) / TB;
    int nblk_edges = (N_EDGES + TB - 1) / TB;

    k_probe<<<1, 32>>>((const int*)ei);
    k_zero<<<nblk_nodes, TB>>>();
    k_count<<<nblk_edges, TB>>>(ei);
    k_dinv<<<nblk_nodes, TB>>>();
    k_scan1<<<SCAN_NB, SCAN_B>>>();
    k_scan2<<<1, 256>>>();
    k_scan3<<<SCAN_NB, SCAN_B>>>();
    k_scatter<<<nblk_edges, TB>>>(ei);

    // 2 hops: warp per node
    int nblk_prop = (N_NODES * 32 + TB - 1) / TB;
    k_prop<<<nblk_prop, TB>>>(x4, 0);
    k_prop<<<nblk_prop, TB>>>(x4, 1);

    // classifier + fused log_softmax: thread per node
    k_classify<<<nblk_nodes, TB>>>(W4, b, out);
}

// round 8
// speedup vs baseline: 1.3182x; 1.3182x over previous
#include <cuda_runtime.h>
#include <math.h>

// Problem constants (fixed by the dataset)
#define N_NODES   170000
#define N_EDGES   1200000
#define D_FEAT    128
#define N_CLASSES 40
#define D4        (D_FEAT / 4)    // 32 float4 per x row
#define C4        (N_CLASSES / 4) // 10 float4 per z row (160 B, 16B-aligned)

#define SCAN_B  1024
#define SCAN_NB ((N_NODES + SCAN_B - 1) / SCAN_B)   // 167

// ---- scratch (device globals; no allocations allowed) ----
__device__ float4 g_zs0[(size_t)N_NODES * C4];   // 27.2 MB  (dinv-scaled projected feats)
__device__ float4 g_zs1[(size_t)N_NODES * C4];   // 27.2 MB  (dinv-scaled hop-1 output)
__device__ int    g_deg[N_NODES];
__device__ int    g_pos[N_NODES];
__device__ int    g_off[N_NODES + 1];
__device__ int    g_bsum[SCAN_NB];
__device__ int    g_srcs[N_EDGES];
__device__ float  g_dinv[N_NODES];
__device__ int    g_is64;   // 1 if edge_index is int64, 0 if int32

// ---- edge accessor: dtype decided at runtime by probe ----
__device__ __forceinline__ int edge_at(const void* ei, int is64, int idx) {
    if (is64) return (int)((const long long*)ei)[idx];
    return ((const int*)ei)[idx];
}
__device__ __forceinline__ int clampN(int v) {
    return ((unsigned)v < (unsigned)N_NODES) ? v : 0;
}

// ---- 0. probe edge dtype: int64 data has all-zero high (odd int32) words ----
__global__ void k_probe(const int* __restrict__ ei32) {
    int lane = threadIdx.x;           // 32 threads
    int w0 = ei32[2 * lane + 1];
    int w1 = ei32[2 * (lane + 32) + 1];
    unsigned nz = __ballot_sync(0xffffffffu, (w0 | w1) != 0);
    if (lane == 0) g_is64 = (nz == 0u) ? 1 : 0;
}

// ---- 1. zero counters ----
__global__ void k_zero() {
    int i = blockIdx.x * blockDim.x + threadIdx.x;
    if (i < N_NODES) { g_deg[i] = 0; g_pos[i] = 0; }
}

// ---- 2. in-degree histogram over dst ----
__global__ void k_count(const void* __restrict__ ei) {
    int e = blockIdx.x * blockDim.x + threadIdx.x;
    int is64 = g_is64;
    if (e < N_EDGES) {
        int d = clampN(edge_at(ei, is64, N_EDGES + e));
        atomicAdd(&g_deg[d], 1);
    }
}

// ---- 3. dinv = rsqrt(indeg + 1)  (self-loop included) ----
__global__ void k_dinv() {
    int i = blockIdx.x * blockDim.x + threadIdx.x;
    if (i < N_NODES) g_dinv[i] = rsqrtf((float)(g_deg[i] + 1));
}

// ---- 4-6. exclusive scan of g_deg -> g_off (3-phase) ----
__global__ void k_scan1() {
    __shared__ int sh[SCAN_B];
    int i = blockIdx.x * SCAN_B + threadIdx.x;
    int v = (i < N_NODES) ? g_deg[i] : 0;
    sh[threadIdx.x] = v;
    __syncthreads();
    for (int d = 1; d < SCAN_B; d <<= 1) {
        int t = (threadIdx.x >= d) ? sh[threadIdx.x - d] : 0;
        __syncthreads();
        sh[threadIdx.x] += t;
        __syncthreads();
    }
    if (i < N_NODES) g_off[i] = sh[threadIdx.x] - v;   // exclusive
    if (threadIdx.x == SCAN_B - 1) g_bsum[blockIdx.x] = sh[SCAN_B - 1];
}

__global__ void k_scan2() {
    __shared__ int sh[256];
    int tid = threadIdx.x;
    int v = (tid < SCAN_NB) ? g_bsum[tid] : 0;
    sh[tid] = v;
    __syncthreads();
    for (int d = 1; d < 256; d <<= 1) {
        int t = (tid >= d) ? sh[tid - d] : 0;
        __syncthreads();
        sh[tid] += t;
        __syncthreads();
    }
    if (tid < SCAN_NB) g_bsum[tid] = sh[tid] - v;      // exclusive block offsets
}

__global__ void k_scan3() {
    int i = blockIdx.x * SCAN_B + threadIdx.x;
    if (i < N_NODES) g_off[i] += g_bsum[blockIdx.x];
    if (i == 0) g_off[N_NODES] = N_EDGES;
}

// ---- 7. scatter edges into CSR-by-dst ----
__global__ void k_scatter(const void* __restrict__ ei) {
    int e = blockIdx.x * blockDim.x + threadIdx.x;
    int is64 = g_is64;
    if (e < N_EDGES) {
        int s = clampN(edge_at(ei, is64, e));
        int d = clampN(edge_at(ei, is64, N_EDGES + e));
        int p = g_off[d] + atomicAdd(&g_pos[d], 1);
        g_srcs[p] = s;
    }
}

// ---- 8. project X(128) -> zs0(40) = dinv[n] * (X[n] . W^T), thread per node ----
// Computed in two 20-class halves to cap live registers => no spill.
__global__ void __launch_bounds__(256) k_project(const float4* __restrict__ x4,
                                                 const float4* __restrict__ W4) {
    __shared__ float4 sW[N_CLASSES][D4];   // 20 KB
    for (int i = threadIdx.x; i < N_CLASSES * D4; i += blockDim.x)
        (&sW[0][0])[i] = W4[i];
    __syncthreads();

    int node = blockIdx.x * blockDim.x + threadIdx.x;
    if (node >= N_NODES) return;

    const float4* h = x4 + (size_t)node * D4;
    float di = g_dinv[node];
    float4* z = g_zs0 + (size_t)node * C4;

    #pragma unroll 1
    for (int half = 0; half < 2; half++) {
        float acc[20];
        #pragma unroll
        for (int c = 0; c < 20; c++) acc[c] = 0.f;

        #pragma unroll 2
        for (int k = 0; k < D4; k++) {
            float4 hv = h[k];                 // half 2: L1 hit (just touched)
            #pragma unroll
            for (int c = 0; c < 20; c++) {
                float4 w = sW[half * 20 + c][k];   // broadcast
                acc[c] = fmaf(hv.x, w.x, acc[c]);
                acc[c] = fmaf(hv.y, w.y, acc[c]);
                acc[c] = fmaf(hv.z, w.z, acc[c]);
                acc[c] = fmaf(hv.w, w.w, acc[c]);
            }
        }

        #pragma unroll
        for (int c = 0; c < 5; c++) {
            float4 v;
            v.x = di * acc[4 * c + 0];
            v.y = di * acc[4 * c + 1];
            v.z = di * acc[4 * c + 2];
            v.w = di * acc[4 * c + 3];
            z[half * 5 + c] = v;
        }
    }
}

// ---- 9. propagation hop on 40-dim rows: warp per node ----
// Buffers selected INSIDE device code (device symbols must not be passed from host!).
// t[i] = sum_{s->i} zin[s] + zin[i]   (zin rows are pre-scaled by dinv)
// pass0:  zs1[i] = dinv[i]^2 * t[i]
// pass1:  logits = dinv[i] * t[i] + b; out = log_softmax(logits)
__global__ void __launch_bounds__(256) k_hop(int pass,
                                             const float* __restrict__ b,
                                             float*       __restrict__ out) {
    const float* zin  = (pass == 0) ? (const float*)g_zs0 : (const float*)g_zs1;

    int gw = (blockIdx.x * blockDim.x + threadIdx.x) >> 5;
    if (gw >= N_NODES) return;
    int lane = threadIdx.x & 31;
    bool hi = lane < (N_CLASSES - 32);     // lanes 0..7 also carry classes 32..39

    int beg = g_off[gw];
    int end = g_off[gw + 1];

    // self term
    const float* zi = zin + (size_t)gw * N_CLASSES;
    float a0 = zi[lane];
    float a1 = hi ? zi[32 + lane] : 0.f;

    // gather-sum over in-edges, 2x unrolled for MLP
    int p = beg;
    for (; p + 1 < end; p += 2) {
        int s0 = g_srcs[p];
        int s1 = g_srcs[p + 1];
        const float* z0 = zin + (size_t)s0 * N_CLASSES;
        const float* z1 = zin + (size_t)s1 * N_CLASSES;
        float u0 = z0[lane];
        float v0 = z1[lane];
        float u1 = hi ? z0[32 + lane] : 0.f;
        float v1 = hi ? z1[32 + lane] : 0.f;
        a0 += u0 + v0;
        a1 += u1 + v1;
    }
    if (p < end) {
        const float* z0 = zin + (size_t)g_srcs[p] * N_CLASSES;
        a0 += z0[lane];
        if (hi) a1 += z0[32 + lane];
    }

    float di = g_dinv[gw];
    if (pass == 0) {
        float di2 = di * di;
        float* zo = (float*)g_zs1 + (size_t)gw * N_CLASSES;
        zo[lane] = di2 * a0;
        if (hi) zo[32 + lane] = di2 * a1;
    } else {
        float l0 = fmaf(di, a0, b[lane]);
        float l1 = hi ? fmaf(di, a1, b[32 + lane]) : -INFINITY;

        float m = fmaxf(l0, l1);
        #pragma unroll
        for (int d = 16; d >= 1; d >>= 1)
            m = fmaxf(m, __shfl_xor_sync(0xffffffffu, m, d));

        float s = __expf(l0 - m) + (hi ? __expf(l1 - m) : 0.f);
        #pragma unroll
        for (int d = 16; d >= 1; d >>= 1)
            s += __shfl_xor_sync(0xffffffffu, s, d);

        float lse = m + logf(s);
        float* o = out + (size_t)gw * N_CLASSES;
        o[lane] = l0 - lse;
        if (hi) o[32 + lane] = l1 - lse;
    }
}

extern "C" void kernel_launch(void* const* d_in, const int* in_sizes, int n_in,
                              void* d_out, int out_size) {
    const float4* x4  = (const float4*)d_in[0];
    const void*   ei  = d_in[1];
    const float4* W4  = (const float4*)d_in[2];
    const float*  b   = (const float*)d_in[3];
    float*        out = (float*)d_out;
    (void)in_sizes; (void)n_in; (void)out_size;

    const int TB = 256;
    int nblk_nodes = (N_NODES + TB - 1) / TB;
    int nblk_edges = (N_EDGES + TB - 1) / TB;

    k_probe<<<1, 32>>>((const int*)ei);
    k_zero<<<nblk_nodes, TB>>>();
    k_count<<<nblk_edges, TB>>>(ei);
    k_dinv<<<nblk_nodes, TB>>>();
    // project can run as soon as dinv is ready (independent of CSR build)
    k_project<<<nblk_nodes, TB>>>(x4, W4);
    k_scan1<<<SCAN_NB, SCAN_B>>>();
    k_scan2<<<1, 256>>>();
    k_scan3<<<SCAN_NB, SCAN_B>>>();
    k_scatter<<<nblk_edges, TB>>>(ei);

    // 2 hops on 40-dim rows: warp per node; pass 1 fuses bias + log_softmax
    int nblk_prop = (N_NODES * 32 + TB - 1) / TB;
    k_hop<<<nblk_prop, TB>>>(0, b, out);
    k_hop<<<nblk_prop, TB>>>(1, b, out);
}

// round 9
// speedup vs baseline: 1.4468x; 1.0976x over previous
#include <cuda_runtime.h>
#include <math.h>

// Problem constants (fixed by the dataset)
#define N_NODES   170000
#define N_EDGES   1200000
#define D_FEAT    128
#define N_CLASSES 40
#define D4        (D_FEAT / 4)    // 32 float4 per x row
#define C4        (N_CLASSES / 4) // 10 float4 per z row (160 B)

#define SCAN_B  1024
#define SCAN_NB ((N_NODES + SCAN_B - 1) / SCAN_B)   // 167

// ---- scratch (device globals; no allocations allowed) ----
__device__ float4 g_zs0[(size_t)N_NODES * C4];   // 27.2 MB  (dinv-scaled projected feats)
__device__ float4 g_zs1[(size_t)N_NODES * C4];   // 27.2 MB  (dinv-scaled hop-1 output)
__device__ int    g_deg[N_NODES];
__device__ int    g_pos[N_NODES];
__device__ int    g_off[N_NODES + 1];
__device__ int    g_bsum[SCAN_NB];
__device__ int    g_srcs[N_EDGES];
__device__ float  g_dinv[N_NODES];
__device__ int    g_is64;   // 1 if edge_index is int64, 0 if int32

// ---- edge accessor: dtype decided at runtime by probe ----
__device__ __forceinline__ int edge_at(const void* ei, int is64, int idx) {
    if (is64) return (int)((const long long*)ei)[idx];
    return ((const int*)ei)[idx];
}
__device__ __forceinline__ int clampN(int v) {
    return ((unsigned)v < (unsigned)N_NODES) ? v : 0;
}

// ---- 1. zero counters + (block 0, warp 0) probe edge dtype ----
// int64 edge data has all-zero high (odd int32) words.
__global__ void k_zero(const int* __restrict__ ei32) {
    if (blockIdx.x == 0 && threadIdx.x < 32) {
        int lane = threadIdx.x;
        int w0 = ei32[2 * lane + 1];
        int w1 = ei32[2 * (lane + 32) + 1];
        unsigned nz = __ballot_sync(0xffffffffu, (w0 | w1) != 0);
        if (lane == 0) g_is64 = (nz == 0u) ? 1 : 0;
    }
    int i = blockIdx.x * blockDim.x + threadIdx.x;
    if (i < N_NODES) { g_deg[i] = 0; g_pos[i] = 0; }
}

// ---- 2. in-degree histogram over dst ----
__global__ void k_count(const void* __restrict__ ei) {
    int e = blockIdx.x * blockDim.x + threadIdx.x;
    int is64 = g_is64;
    if (e < N_EDGES) {
        int d = clampN(edge_at(ei, is64, N_EDGES + e));
        atomicAdd(&g_deg[d], 1);
    }
}

// ---- 3-5. exclusive scan of g_deg -> g_off (3-phase); scan1 also emits dinv ----
__global__ void k_scan1() {
    __shared__ int sh[SCAN_B];
    int i = blockIdx.x * SCAN_B + threadIdx.x;
    int v = (i < N_NODES) ? g_deg[i] : 0;
    if (i < N_NODES) g_dinv[i] = rsqrtf((float)(v + 1));   // fused dinv
    sh[threadIdx.x] = v;
    __syncthreads();
    for (int d = 1; d < SCAN_B; d <<= 1) {
        int t = (threadIdx.x >= d) ? sh[threadIdx.x - d] : 0;
        __syncthreads();
        sh[threadIdx.x] += t;
        __syncthreads();
    }
    if (i < N_NODES) g_off[i] = sh[threadIdx.x] - v;   // exclusive
    if (threadIdx.x == SCAN_B - 1) g_bsum[blockIdx.x] = sh[SCAN_B - 1];
}

__global__ void k_scan2() {
    __shared__ int sh[256];
    int tid = threadIdx.x;
    int v = (tid < SCAN_NB) ? g_bsum[tid] : 0;
    sh[tid] = v;
    __syncthreads();
    for (int d = 1; d < 256; d <<= 1) {
        int t = (tid >= d) ? sh[tid - d] : 0;
        __syncthreads();
        sh[tid] += t;
        __syncthreads();
    }
    if (tid < SCAN_NB) g_bsum[tid] = sh[tid] - v;      // exclusive block offsets
}

__global__ void k_scan3() {
    int i = blockIdx.x * SCAN_B + threadIdx.x;
    if (i < N_NODES) g_off[i] += g_bsum[blockIdx.x];
    if (i == 0) g_off[N_NODES] = N_EDGES;
}

// ---- 6. project X(128) -> zs0(40) = dinv[n] * (X[n] . W^T), thread per node ----
// Computed in two 20-class halves to cap live registers => no spill.
__global__ void __launch_bounds__(256) k_project(const float4* __restrict__ x4,
                                                 const float4* __restrict__ W4) {
    __shared__ float4 sW[N_CLASSES][D4];   // 20 KB
    for (int i = threadIdx.x; i < N_CLASSES * D4; i += blockDim.x)
        (&sW[0][0])[i] = W4[i];
    __syncthreads();

    int node = blockIdx.x * blockDim.x + threadIdx.x;
    if (node >= N_NODES) return;

    const float4* h = x4 + (size_t)node * D4;
    float di = g_dinv[node];
    float4* z = g_zs0 + (size_t)node * C4;

    #pragma unroll 1
    for (int half = 0; half < 2; half++) {
        float acc[20];
        #pragma unroll
        for (int c = 0; c < 20; c++) acc[c] = 0.f;

        #pragma unroll 2
        for (int k = 0; k < D4; k++) {
            float4 hv = h[k];                 // half 2: L1 hit (just touched)
            #pragma unroll
            for (int c = 0; c < 20; c++) {
                float4 w = sW[half * 20 + c][k];   // broadcast
                acc[c] = fmaf(hv.x, w.x, acc[c]);
                acc[c] = fmaf(hv.y, w.y, acc[c]);
                acc[c] = fmaf(hv.z, w.z, acc[c]);
                acc[c] = fmaf(hv.w, w.w, acc[c]);
            }
        }

        #pragma unroll
        for (int c = 0; c < 5; c++) {
            float4 v;
            v.x = di * acc[4 * c + 0];
            v.y = di * acc[4 * c + 1];
            v.z = di * acc[4 * c + 2];
            v.w = di * acc[4 * c + 3];
            z[half * 5 + c] = v;
        }
    }
}

// ---- 7. scatter edges into CSR-by-dst ----
__global__ void k_scatter(const void* __restrict__ ei) {
    int e = blockIdx.x * blockDim.x + threadIdx.x;
    int is64 = g_is64;
    if (e < N_EDGES) {
        int s = clampN(edge_at(ei, is64, e));
        int d = clampN(edge_at(ei, is64, N_EDGES + e));
        int p = g_off[d] + atomicAdd(&g_pos[d], 1);
        g_srcs[p] = s;
    }
}

// ---- 8. propagation hop: TWO nodes per warp, float4 gathers ----
// Half-warp (16 lanes) per node; lanes 0..9 of each half hold the 10 float4
// of the 160B row. t[i] = sum_{s->i} zin[s] + zin[i] (rows pre-scaled by dinv).
// pass0:  zs1[i] = dinv[i]^2 * t[i]
// pass1:  logits = dinv[i] * t[i] + b; out = log_softmax(logits)
__global__ void __launch_bounds__(256) k_hop(int pass,
                                             const float4* __restrict__ b4,
                                             float4*       __restrict__ out4) {
    const float4* zin = (pass == 0) ? (const float4*)g_zs0 : (const float4*)g_zs1;

    int warp = (blockIdx.x * blockDim.x + threadIdx.x) >> 5;
    int lane = threadIdx.x & 31;
    int half = lane >> 4;          // 0 or 1
    int hl   = lane & 15;          // lane within half
    int node = warp * 2 + half;    // N_NODES even; grid sized exactly
    bool act = hl < C4;            // lanes 0..9 active

    int beg = act ? g_off[node]     : 0;
    int end = act ? g_off[node + 1] : 0;

    // self term
    float4 a = make_float4(0.f, 0.f, 0.f, 0.f);
    if (act) a = zin[(size_t)node * C4 + hl];

    // gather-sum over in-edges, 2x unrolled for MLP
    int p = beg;
    for (; p + 1 < end; p += 2) {
        int s0 = g_srcs[p];
        int s1 = g_srcs[p + 1];
        float4 u = zin[(size_t)s0 * C4 + hl];
        float4 v = zin[(size_t)s1 * C4 + hl];
        a.x += u.x + v.x;
        a.y += u.y + v.y;
        a.z += u.z + v.z;
        a.w += u.w + v.w;
    }
    if (p < end) {
        float4 u = zin[(size_t)g_srcs[p] * C4 + hl];
        a.x += u.x; a.y += u.y; a.z += u.z; a.w += u.w;
    }

    float di = act ? g_dinv[node] : 0.f;
    if (pass == 0) {
        if (act) {
            float di2 = di * di;
            float4 o;
            o.x = di2 * a.x; o.y = di2 * a.y; o.z = di2 * a.z; o.w = di2 * a.w;
            g_zs1[(size_t)node * C4 + hl] = o;
        }
    } else {
        float4 l = make_float4(-INFINITY, -INFINITY, -INFINITY, -INFINITY);
        if (act) {
            float4 bb = b4[hl];
            l.x = fmaf(di, a.x, bb.x);
            l.y = fmaf(di, a.y, bb.y);
            l.z = fmaf(di, a.z, bb.z);
            l.w = fmaf(di, a.w, bb.w);
        }

        // component-wise max/sum reduced across the 16-lane half
        float m = fmaxf(fmaxf(l.x, l.y), fmaxf(l.z, l.w));
        #pragma unroll
        for (int d = 8; d >= 1; d >>= 1)
            m = fmaxf(m, __shfl_xor_sync(0xffffffffu, m, d));

        float s = __expf(l.x - m) + __expf(l.y - m) +
                  __expf(l.z - m) + __expf(l.w - m);   // inactive: 4*exp(-inf)=0
        #pragma unroll
        for (int d = 8; d >= 1; d >>= 1)
            s += __shfl_xor_sync(0xffffffffu, s, d);

        float lse = m + logf(s);
        if (act) {
            float4 o;
            o.x = l.x - lse; o.y = l.y - lse; o.z = l.z - lse; o.w = l.w - lse;
            out4[(size_t)node * C4 + hl] = o;
        }
    }
}

extern "C" void kernel_launch(void* const* d_in, const int* in_sizes, int n_in,
                              void* d_out, int out_size) {
    const float4* x4  = (const float4*)d_in[0];
    const void*   ei  = d_in[1];
    const float4* W4  = (const float4*)d_in[2];
    const float4* b4  = (const float4*)d_in[3];
    float4*       out4 = (float4*)d_out;
    (void)in_sizes; (void)n_in; (void)out_size;

    const int TB = 256;
    int nblk_nodes = (N_NODES + TB - 1) / TB;
    int nblk_edges = (N_EDGES + TB - 1) / TB;

    k_zero<<<nblk_nodes, TB>>>((const int*)ei);   // + dtype probe
    k_count<<<nblk_edges, TB>>>(ei);
    k_scan1<<<SCAN_NB, SCAN_B>>>();               // + dinv
    k_scan2<<<1, 256>>>();
    k_scan3<<<SCAN_NB, SCAN_B>>>();
    k_project<<<nblk_nodes, TB>>>(x4, W4);
    k_scatter<<<nblk_edges, TB>>>(ei);

    // 2 hops: two nodes per warp => N_NODES/2 warps
    int nblk_hop = (N_NODES / 2) * 32 / TB;       // 10625 blocks exactly
    k_hop<<<nblk_hop, TB>>>(0, b4, out4);
    k_hop<<<nblk_hop, TB>>>(1, b4, out4);
}